// round 2
// baseline (speedup 1.0000x reference)
#include <cuda_runtime.h>

// VTBPR fused kernel:
//   score[b] = item_beta[i] + user_beta[u] + <ug,ig> + <tv,vf_b> + <tt,tf_b>
//   metapath[b,0,p,l,:] = ug if path_type[b,p,l]==0, ig if ==1, else 0
//
// Layout assumption: d_out = [ score (B floats) | metapath (B*16*512 floats) ]
//
// One CTA per batch row. 128 threads; thread t owns float4 lane t of the
// 512-dim vectors (512 f32 = 128 float4). All loads/stores coalesced.

#define HIDDEN 512
#define VEC    (HIDDEN / 4)   // 128 float4 lanes
#define PL     16             // P*L

__global__ __launch_bounds__(VEC, 8)
void vtbpr_kernel(const float* __restrict__ user_gama,
                  const float* __restrict__ item_gama,
                  const float* __restrict__ user_beta,
                  const float* __restrict__ item_beta,
                  const float* __restrict__ theta_user_visual,
                  const float* __restrict__ theta_user_text,
                  const float* __restrict__ visual_features,
                  const float* __restrict__ textural_features,
                  const int*   __restrict__ user_idx,
                  const int*   __restrict__ item_idx,
                  const int*   __restrict__ path_type,
                  float* __restrict__ out,
                  int B)
{
    const int b   = blockIdx.x;
    const int tid = threadIdx.x;           // 0..127

    __shared__ int   pt[PL];
    __shared__ float wsum[VEC / 32];

    const int u = user_idx[b];
    const int i = item_idx[b];

    if (tid < PL) pt[tid] = path_type[b * PL + tid];

    const float4* ug_p = (const float4*)(user_gama         + (size_t)u * HIDDEN);
    const float4* ig_p = (const float4*)(item_gama         + (size_t)i * HIDDEN);
    const float4* tv_p = (const float4*)(theta_user_visual + (size_t)u * HIDDEN);
    const float4* tt_p = (const float4*)(theta_user_text   + (size_t)u * HIDDEN);
    const float4* vf_p = (const float4*)(visual_features   + (size_t)b * HIDDEN);
    const float4* tf_p = (const float4*)(textural_features + (size_t)b * HIDDEN);

    const float4 ug4 = ug_p[tid];
    const float4 ig4 = ig_p[tid];
    const float4 tv4 = tv_p[tid];
    const float4 tt4 = tt_p[tid];
    const float4 vf4 = vf_p[tid];
    const float4 tf4 = tf_p[tid];

    // Partial of the three dot products
    float partial =
        ug4.x * ig4.x + ug4.y * ig4.y + ug4.z * ig4.z + ug4.w * ig4.w +
        tv4.x * vf4.x + tv4.y * vf4.y + tv4.z * vf4.z + tv4.w * vf4.w +
        tt4.x * tf4.x + tt4.y * tf4.y + tt4.z * tf4.z + tt4.w * tf4.w;

    // Warp reduce
    #pragma unroll
    for (int off = 16; off > 0; off >>= 1)
        partial += __shfl_xor_sync(0xFFFFFFFFu, partial, off);

    if ((tid & 31) == 0) wsum[tid >> 5] = partial;
    __syncthreads();

    if (tid == 0) {
        float s = user_beta[u] + item_beta[i];
        #pragma unroll
        for (int w = 0; w < VEC / 32; w++) s += wsum[w];
        out[b] = s;
    }

    // Metapath scatter: 16 segments of 512 floats, fully coalesced STG.128
    float4* mp = (float4*)(out + B + (size_t)b * PL * HIDDEN);
    const float4 zero4 = make_float4(0.f, 0.f, 0.f, 0.f);

    #pragma unroll
    for (int j = 0; j < PL; j++) {
        const int t = pt[j];
        const float4 v = (t == 0) ? ug4 : ((t == 1) ? ig4 : zero4);
        mp[(size_t)j * VEC + tid] = v;
    }
}

extern "C" void kernel_launch(void* const* d_in, const int* in_sizes, int n_in,
                              void* d_out, int out_size)
{
    const float* user_gama          = (const float*)d_in[0];
    const float* item_gama          = (const float*)d_in[1];
    const float* user_beta          = (const float*)d_in[2];
    const float* item_beta          = (const float*)d_in[3];
    const float* theta_user_visual  = (const float*)d_in[4];
    const float* theta_user_text    = (const float*)d_in[5];
    const float* visual_features    = (const float*)d_in[6];
    const float* textural_features  = (const float*)d_in[7];
    const int*   user_idx           = (const int*)d_in[8];
    const int*   item_idx           = (const int*)d_in[9];
    const int*   path_type          = (const int*)d_in[10];

    const int B = in_sizes[8];  // 8192

    vtbpr_kernel<<<B, VEC>>>(user_gama, item_gama, user_beta, item_beta,
                             theta_user_visual, theta_user_text,
                             visual_features, textural_features,
                             user_idx, item_idx, path_type,
                             (float*)d_out, B);
}